// round 3
// baseline (speedup 1.0000x reference)
#include <cuda_runtime.h>

#define NROWS 14400   // 16 * 900
#define NC    91
#define MT    1600
#define TN    8
#define EPSF  1e-8f

// Scratch: per-(row, class) focal cost, computed once (5.24 MB)
__device__ float g_cc[NROWS * NC];

__global__ __launch_bounds__(256) void prep_cc_kernel(const float* __restrict__ logits) {
    int i = blockIdx.x * blockDim.x + threadIdx.x;
    if (i >= NROWS * NC) return;
    float x = logits[i];
    float p = 1.0f / (1.0f + expf(-x));
    float omp = 1.0f - p;
    float pos = 0.25f * omp * omp * (-logf(p + EPSF));
    float neg = 0.75f * p * p * (-log1pf(-p + EPSF));
    g_cc[i] = pos - neg;
}

__global__ __launch_bounds__(256) void cost_kernel(
    const float* __restrict__ pred_boxes,  // [NROWS, 4] cxcywh
    const int*   __restrict__ tgt_ids,     // [MT] int32
    const float* __restrict__ tgt_bbox,    // [MT, 4] cxcywh
    float*       __restrict__ out)         // [NROWS, MT]
{
    __shared__ float4 s_tb[MT];        // tgt cxcywh
    __shared__ int    s_tid[MT];       // tgt class ids
    __shared__ float  s_cc[TN * NC];   // focal cost slice for this block's rows
    __shared__ float4 s_pb[TN];        // pred cxcywh for this block's rows

    const int tid = threadIdx.x;
    const int n0  = blockIdx.x * TN;

    for (int i = tid; i < MT; i += 256) {
        s_tb[i] = ((const float4*)tgt_bbox)[i];
        int id  = tgt_ids[i];
        // defensive clamp: keeps us in-bounds even if dtype assumption is wrong
        s_tid[i] = (id < 0) ? 0 : (id >= NC ? NC - 1 : id);
    }
    for (int i = tid; i < TN * NC; i += 256) {
        s_cc[i] = g_cc[n0 * NC + i];   // contiguous slab: rows n0..n0+7
    }
    if (tid < TN) s_pb[tid] = ((const float4*)pred_boxes)[n0 + tid];
    __syncthreads();

    // Each thread owns groups of 4 consecutive target columns (float4 stores).
    for (int g = tid; g < MT / 4; g += 256) {
        const int m0 = g * 4;

        // Load tgt data for 4 columns once; reuse across TN rows.
        float tcx[4], tcy[4], tw[4], thh[4];
        float tx0[4], ty0[4], tx1[4], ty1[4], tarea[4];
        int   id[4];
#pragma unroll
        for (int j = 0; j < 4; j++) {
            float4 tb = s_tb[m0 + j];
            tcx[j] = tb.x; tcy[j] = tb.y; tw[j] = tb.z; thh[j] = tb.w;
            tx0[j] = tb.x - 0.5f * tb.z;
            ty0[j] = tb.y - 0.5f * tb.w;
            tx1[j] = tb.x + 0.5f * tb.z;
            ty1[j] = tb.y + 0.5f * tb.w;
            tarea[j] = tb.z * tb.w;
            id[j] = s_tid[m0 + j];
        }

#pragma unroll
        for (int r = 0; r < TN; r++) {
            float4 pb = s_pb[r];
            float px0 = pb.x - 0.5f * pb.z, py0 = pb.y - 0.5f * pb.w;
            float px1 = pb.x + 0.5f * pb.z, py1 = pb.y + 0.5f * pb.w;
            float parea = pb.z * pb.w;

            float4 res;
            float* rp = &res.x;
#pragma unroll
            for (int j = 0; j < 4; j++) {
                // L1 on cxcywh
                float cb = fabsf(pb.x - tcx[j]) + fabsf(pb.y - tcy[j])
                         + fabsf(pb.z - tw[j])  + fabsf(pb.w - thh[j]);
                // Intersection
                float ix0 = fmaxf(px0, tx0[j]), iy0 = fmaxf(py0, ty0[j]);
                float ix1 = fminf(px1, tx1[j]), iy1 = fminf(py1, ty1[j]);
                float iw = fmaxf(ix1 - ix0, 0.0f), ih = fmaxf(iy1 - iy0, 0.0f);
                float inter = iw * ih;
                float uni = parea + tarea[j] - inter;
                float iou = __fdividef(inter, uni);
                // Enclosing box
                float ex0 = fminf(px0, tx0[j]), ey0 = fminf(py0, ty0[j]);
                float ex1 = fmaxf(px1, tx1[j]), ey1 = fmaxf(py1, ty1[j]);
                float ew = fmaxf(ex1 - ex0, 0.0f), eh = fmaxf(ey1 - ey0, 0.0f);
                float earea = ew * eh;
                float giou = iou - __fdividef(earea - uni, earea);
                // Focal class cost gather
                float cc = s_cc[r * NC + id[j]];
                rp[j] = cb + cc - giou;   // bbox + class - giou
            }
            ((float4*)out)[((size_t)(n0 + r) * MT + m0) >> 2] = res;
        }
    }
}

extern "C" void kernel_launch(void* const* d_in, const int* in_sizes, int n_in,
                              void* d_out, int out_size) {
    const float* pred_logits = (const float*)d_in[0];  // [16,900,91]
    const float* pred_boxes  = (const float*)d_in[1];  // [16,900,4]
    const int*   tgt_ids     = (const int*)d_in[2];    // [1600] int32 (harness dtype map)
    const float* tgt_bbox    = (const float*)d_in[3];  // [1600,4]
    float*       out         = (float*)d_out;          // [16,900,1600]

    const int cc_total = NROWS * NC;
    prep_cc_kernel<<<(cc_total + 255) / 256, 256>>>(pred_logits);
    cost_kernel<<<NROWS / TN, 256>>>(pred_boxes, tgt_ids, tgt_bbox, out);
}

// round 5
// speedup vs baseline: 1.1567x; 1.1567x over previous
#include <cuda_runtime.h>

#define NROWS 14400   // 16 * 900
#define NC    91
#define MT    1600
#define TN    8
#define EPSF  1e-8f

// Scratch: per-(row, class) focal cost, computed once (5.24 MB)
__device__ float g_cc[NROWS * NC];

__global__ __launch_bounds__(256) void prep_cc_kernel(const float* __restrict__ logits) {
    int i = blockIdx.x * blockDim.x + threadIdx.x;
    if (i >= NROWS * NC) return;
    float x = logits[i];
    float p = 1.0f / (1.0f + expf(-x));
    float omp = 1.0f - p;
    float pos = 0.25f * omp * omp * (-logf(p + EPSF));
    float neg = 0.75f * p * p * (-log1pf(-p + EPSF));
    g_cc[i] = pos - neg;
}

__global__ __launch_bounds__(256, 3) void cost_kernel(
    const float* __restrict__ pred_boxes,  // [NROWS, 4] cxcywh
    const int*   __restrict__ tgt_ids,     // [MT] int32
    const float* __restrict__ tgt_bbox,    // [MT, 4] cxcywh
    float*       __restrict__ out)         // [NROWS, MT]
{
    __shared__ float4 s_tb[MT];        // tgt cxcywh
    __shared__ int    s_tid[MT];       // tgt class ids
    __shared__ float  s_cc[TN * NC];   // focal cost slice for this block's rows
    __shared__ float4 s_pb[TN];        // pred cxcywh for this block's rows

    const int tid = threadIdx.x;
    const int n0  = blockIdx.x * TN;

    for (int i = tid; i < MT; i += 256) {
        s_tb[i] = ((const float4*)tgt_bbox)[i];
        int id  = tgt_ids[i];
        s_tid[i] = (id < 0) ? 0 : (id >= NC ? NC - 1 : id);
    }
    for (int i = tid; i < TN * NC; i += 256) {
        s_cc[i] = g_cc[n0 * NC + i];
    }
    if (tid < TN) s_pb[tid] = ((const float4*)pred_boxes)[n0 + tid];
    __syncthreads();

    // Each thread owns groups of 4 consecutive target columns (float4 stores).
    for (int g = tid; g < MT / 4; g += 256) {
        const int m0 = g * 4;

        // Per-column cache: cx, cy, half-w, half-h, area, class id (6 regs/col)
        float tcx[4], tcy[4], htw[4], hth[4], ta[4];
        int   id[4];
#pragma unroll
        for (int j = 0; j < 4; j++) {
            float4 tb = s_tb[m0 + j];
            tcx[j] = tb.x;
            tcy[j] = tb.y;
            htw[j] = 0.5f * tb.z;
            hth[j] = 0.5f * tb.w;
            ta[j]  = tb.z * tb.w;
            id[j]  = s_tid[m0 + j];
        }

#pragma unroll
        for (int r = 0; r < TN; r++) {
            float4 pb = s_pb[r];
            float pcx = pb.x, pcy = pb.y;
            float hpw = 0.5f * pb.z, hph = 0.5f * pb.w;
            float pa  = pb.z * pb.w;
            const float* ccrow = &s_cc[r * NC];

            float4 res;
            float* rp = &res.x;
#pragma unroll
            for (int j = 0; j < 4; j++) {
                // Shared terms: center dist + half-size dist (also the L1 cost pieces)
                float dx = fabsf(pcx - tcx[j]);
                float dy = fabsf(pcy - tcy[j]);
                float sx = fabsf(hpw - htw[j]);   // = 0.5*|pw - tw|
                float sy = fabsf(hph - hth[j]);
                // L1 cost: |dcx|+|dcy|+|dw|+|dh| = dx+dy+2*(sx+sy)
                float cb = fmaf(2.0f, sx + sy, dx + dy);
                // Interval overlap identity:
                //   inter_w = max(ax - bx, 0), enclose_w = ax + bx
                //   ax = 0.5*(pw+tw), bx = max(|dcx|, 0.5*|pw-tw|)
                float ax = hpw + htw[j];
                float ay = hph + hth[j];
                float bx = fmaxf(dx, sx);
                float by = fmaxf(dy, sy);
                float iw = fmaxf(ax - bx, 0.0f);
                float ih = fmaxf(ay - by, 0.0f);
                float inter = iw * ih;
                float uni   = pa + ta[j] - inter;
                float ea    = (ax + bx) * (ay + by);   // enclosing area (>= 0 by construction)
                float iou   = __fdividef(inter, uni);
                float q     = __fdividef(uni, ea);
                // cost = cb + cc - giou; giou = iou - 1 + uni/ea
                float cc = ccrow[id[j]];
                rp[j] = cb + cc + (1.0f - iou - q);
            }
            ((float4*)out)[((size_t)(n0 + r) * MT + m0) >> 2] = res;
        }
    }
}

extern "C" void kernel_launch(void* const* d_in, const int* in_sizes, int n_in,
                              void* d_out, int out_size) {
    const float* pred_logits = (const float*)d_in[0];  // [16,900,91]
    const float* pred_boxes  = (const float*)d_in[1];  // [16,900,4]
    const int*   tgt_ids     = (const int*)d_in[2];    // [1600] int32
    const float* tgt_bbox    = (const float*)d_in[3];  // [1600,4]
    float*       out         = (float*)d_out;          // [16,900,1600]

    const int cc_total = NROWS * NC;
    prep_cc_kernel<<<(cc_total + 255) / 256, 256>>>(pred_logits);
    cost_kernel<<<NROWS / TN, 256>>>(pred_boxes, tgt_ids, tgt_bbox, out);
}

// round 8
// speedup vs baseline: 1.2151x; 1.0504x over previous
#include <cuda_runtime.h>

#define NROWS 14400   // 16 * 900
#define NC    91
#define MT    1600
#define TN    8
#define EPSF  1e-8f

// Scratch: per-(row, class) focal cost, computed once (5.24 MB)
__device__ float g_cc[NROWS * NC];

__global__ __launch_bounds__(256) void prep_cc_kernel(const float* __restrict__ logits) {
    int i = blockIdx.x * blockDim.x + threadIdx.x;
    if (i >= NROWS * NC) return;
    float x = logits[i];
    float p = 1.0f / (1.0f + expf(-x));
    float omp = 1.0f - p;
    float pos = 0.25f * omp * omp * (-logf(p + EPSF));
    float neg = 0.75f * p * p * (-log1pf(-p + EPSF));
    g_cc[i] = pos - neg;
}

__global__ __launch_bounds__(256, 4) void cost_kernel(
    const float* __restrict__ pred_boxes,  // [NROWS, 4] cxcywh
    const int*   __restrict__ tgt_ids,     // [MT] int32
    const float* __restrict__ tgt_bbox,    // [MT, 4] cxcywh
    float*       __restrict__ out)         // [NROWS, MT]
{
    __shared__ float4 s_tb[MT];        // tgt (cx, cy, w/2, h/2)
    __shared__ int    s_tid[MT];       // tgt class ids
    __shared__ float  s_cc[TN * NC];   // focal cost slice for this block's rows
    __shared__ float4 s_pb[TN];        // pred (cx, cy, w/2, h/2)

    const int tid = threadIdx.x;
    const int n0  = blockIdx.x * TN;

    for (int i = tid; i < MT; i += 256) {
        float4 tb = ((const float4*)tgt_bbox)[i];
        s_tb[i] = make_float4(tb.x, tb.y, 0.5f * tb.z, 0.5f * tb.w);
        int id  = tgt_ids[i];
        s_tid[i] = (id < 0) ? 0 : (id >= NC ? NC - 1 : id);
    }
    for (int i = tid; i < TN * NC; i += 256) {
        s_cc[i] = g_cc[n0 * NC + i];
    }
    if (tid < TN) {
        float4 pb = ((const float4*)pred_boxes)[n0 + tid];
        s_pb[tid] = make_float4(pb.x, pb.y, 0.5f * pb.z, 0.5f * pb.w);
    }
    __syncthreads();

    // Each thread owns groups of 4 consecutive target columns (float4 stores).
    for (int g = tid; g < MT / 4; g += 256) {
        const int m0 = g * 4;

        // Per-column cache: cx, cy, hw, hh, quarter-area, class id
        float tcx[4], tcy[4], htw[4], hth[4], qta[4];
        int   id[4];
#pragma unroll
        for (int j = 0; j < 4; j++) {
            float4 tb = s_tb[m0 + j];
            tcx[j] = tb.x;
            tcy[j] = tb.y;
            htw[j] = tb.z;
            hth[j] = tb.w;
            qta[j] = tb.z * tb.w;      // = tgt area / 4
            id[j]  = s_tid[m0 + j];
        }

#pragma unroll
        for (int r = 0; r < TN; r++) {
            float4 pb = s_pb[r];
            float pcx = pb.x, pcy = pb.y;
            float hpw = pb.z, hph = pb.w;
            float qpa = hpw * hph;     // pred area / 4
            const float* ccrow = &s_cc[r * NC];

            float4 res;
            float* rp = &res.x;
#pragma unroll
            for (int j = 0; j < 4; j++) {
                // Shared |diff| terms (serve both L1 cost and geometry)
                float dx = fabsf(pcx - tcx[j]);
                float dy = fabsf(pcy - tcy[j]);
                float sx = fabsf(hpw - htw[j]);   // 0.5|pw - tw|
                float sy = fabsf(hph - hth[j]);
                // L1: dx + dy + 2(sx + sy)
                float cb = fmaf(2.0f, sx + sy, dx + dy);
                // Interval identity (halves cancel): overlap_w = (hpw+htw) - max(dx, sx)  [FULL width]
                float ax = hpw + htw[j];
                float ay = hph + hth[j];
                float bx = fmaxf(dx, sx);
                float by = fmaxf(dy, sy);
                float iw = fmaxf(ax - bx, 0.0f);  // full intersection width
                float ih = fmaxf(ay - by, 0.0f);
                float inter = iw * ih;                        // FULL intersection area
                float uni   = fmaf(4.0f, qpa + qta[j], -inter); // FULL union (areas were /4)
                float ea    = (ax + bx) * (ay + by);          // FULL enclosing area
                float iou   = __fdividef(inter, uni);
                float q     = __fdividef(uni, ea);
                // cost = cb + cc - giou = cb + cc + 1 - iou - uni/ea
                float t = cb + ccrow[id[j]];
                rp[j] = (t - q) + (1.0f - iou);
            }
            ((float4*)out)[((size_t)(n0 + r) * MT + m0) >> 2] = res;
        }
    }
}

extern "C" void kernel_launch(void* const* d_in, const int* in_sizes, int n_in,
                              void* d_out, int out_size) {
    const float* pred_logits = (const float*)d_in[0];  // [16,900,91]
    const float* pred_boxes  = (const float*)d_in[1];  // [16,900,4]
    const int*   tgt_ids     = (const int*)d_in[2];    // [1600] int32
    const float* tgt_bbox    = (const float*)d_in[3];  // [1600,4]
    float*       out         = (float*)d_out;          // [16,900,1600]

    const int cc_total = NROWS * NC;
    prep_cc_kernel<<<(cc_total + 255) / 256, 256>>>(pred_logits);
    cost_kernel<<<NROWS / TN, 256>>>(pred_boxes, tgt_ids, tgt_bbox, out);
}

// round 9
// speedup vs baseline: 1.2529x; 1.0312x over previous
#include <cuda_runtime.h>

#define NROWS 14400   // 16 * 900
#define NC    91
#define MT    1600
#define TN    8
#define EPSF  1e-8f

__global__ __launch_bounds__(256, 4) void cost_kernel(
    const float* __restrict__ pred_logits, // [NROWS, NC]
    const float* __restrict__ pred_boxes,  // [NROWS, 4] cxcywh
    const int*   __restrict__ tgt_ids,     // [MT] int32
    const float* __restrict__ tgt_bbox,    // [MT, 4] cxcywh
    float*       __restrict__ out)         // [NROWS, MT]
{
    __shared__ float4 s_tb[MT];        // tgt (cx, cy, w/2, h/2)
    __shared__ int    s_tid[MT];       // tgt class ids
    __shared__ float  s_cc[TN * NC];   // focal cost slice for this block's rows
    __shared__ float4 s_pb[TN];        // pred (cx, cy, w/2, h/2)

    const int tid = threadIdx.x;
    const int n0  = blockIdx.x * TN;

    for (int i = tid; i < MT; i += 256) {
        float4 tb = ((const float4*)tgt_bbox)[i];
        s_tb[i] = make_float4(tb.x, tb.y, 0.5f * tb.z, 0.5f * tb.w);
        int id  = tgt_ids[i];
        s_tid[i] = (id < 0) ? 0 : (id >= NC ? NC - 1 : id);
    }
    // Fused focal-cost prep for this block's 8 rows (contiguous logits slab)
    for (int i = tid; i < TN * NC; i += 256) {
        float x = pred_logits[n0 * NC + i];
        float p = 1.0f / (1.0f + expf(-x));
        float omp = 1.0f - p;
        float pos = 0.25f * omp * omp * (-logf(p + EPSF));
        float neg = 0.75f * p * p * (-log1pf(-p + EPSF));
        s_cc[i] = pos - neg;
    }
    if (tid < TN) {
        float4 pb = ((const float4*)pred_boxes)[n0 + tid];
        s_pb[tid] = make_float4(pb.x, pb.y, 0.5f * pb.z, 0.5f * pb.w);
    }
    __syncthreads();

    // Each thread owns groups of 4 consecutive target columns (float4 stores).
    for (int g = tid; g < MT / 4; g += 256) {
        const int m0 = g * 4;

        // Per-column cache: cx, cy, hw, hh, quarter-area, class id
        float tcx[4], tcy[4], htw[4], hth[4], qta[4];
        int   id[4];
#pragma unroll
        for (int j = 0; j < 4; j++) {
            float4 tb = s_tb[m0 + j];
            tcx[j] = tb.x;
            tcy[j] = tb.y;
            htw[j] = tb.z;
            hth[j] = tb.w;
            qta[j] = tb.z * tb.w;      // tgt area / 4
            id[j]  = s_tid[m0 + j];
        }

#pragma unroll
        for (int r = 0; r < TN; r++) {
            float4 pb = s_pb[r];
            float pcx = pb.x, pcy = pb.y;
            float hpw = pb.z, hph = pb.w;
            float qpa = hpw * hph;     // pred area / 4
            const float* ccrow = &s_cc[r * NC];

            float4 res;
            float* rp = &res.x;
#pragma unroll
            for (int j = 0; j < 4; j++) {
                // Shared |diff| terms (serve both L1 cost and geometry)
                float dx = fabsf(pcx - tcx[j]);
                float dy = fabsf(pcy - tcy[j]);
                float sx = fabsf(hpw - htw[j]);   // 0.5|pw - tw|
                float sy = fabsf(hph - hth[j]);
                // L1: dx + dy + 2(sx + sy)
                float cb = fmaf(2.0f, sx + sy, dx + dy);
                // Interval identity (halves cancel): overlap_w = (hpw+htw) - max(dx, sx)
                float ax = hpw + htw[j];
                float ay = hph + hth[j];
                float bx = fmaxf(dx, sx);
                float by = fmaxf(dy, sy);
                float iw = fmaxf(ax - bx, 0.0f);  // full intersection width
                float ih = fmaxf(ay - by, 0.0f);
                float inter = iw * ih;                          // full intersection area
                float uni   = fmaf(4.0f, qpa + qta[j], -inter); // full union
                float ea    = (ax + bx) * (ay + by);            // full enclosing area
                // Single reciprocal serves both ratios:
                //   iou = inter/uni = inter*ea * rcp(uni*ea)
                //   q   = uni/ea    = uni*uni  * rcp(uni*ea)
                float denom = uni * ea;
                float rd;
                asm("rcp.approx.f32 %0, %1;" : "=f"(rd) : "f"(denom));
                float iou = inter * ea * rd;
                float q   = uni * uni * rd;
                // cost = cb + cc + 1 - iou - uni/ea
                float t = cb + ccrow[id[j]];
                rp[j] = (t - q) + (1.0f - iou);
            }
            ((float4*)out)[((size_t)(n0 + r) * MT + m0) >> 2] = res;
        }
    }
}

extern "C" void kernel_launch(void* const* d_in, const int* in_sizes, int n_in,
                              void* d_out, int out_size) {
    const float* pred_logits = (const float*)d_in[0];  // [16,900,91]
    const float* pred_boxes  = (const float*)d_in[1];  // [16,900,4]
    const int*   tgt_ids     = (const int*)d_in[2];    // [1600] int32
    const float* tgt_bbox    = (const float*)d_in[3];  // [1600,4]
    float*       out         = (float*)d_out;          // [16,900,1600]

    cost_kernel<<<NROWS / TN, 256>>>(pred_logits, pred_boxes, tgt_ids, tgt_bbox, out);
}

// round 10
// speedup vs baseline: 1.3432x; 1.0721x over previous
#include <cuda_runtime.h>

#define NROWS 14400   // 16 * 900
#define NC    91
#define MT    1600
#define TN    8
#define EPSF  1e-8f

__global__ __launch_bounds__(256, 4) void cost_kernel(
    const float* __restrict__ pred_logits, // [NROWS, NC]
    const float* __restrict__ pred_boxes,  // [NROWS, 4] cxcywh
    const int*   __restrict__ tgt_ids,     // [MT] int32
    const float* __restrict__ tgt_bbox,    // [MT, 4] cxcywh
    float*       __restrict__ out)         // [NROWS, MT]
{
    __shared__ float4 s_tb[MT];        // tgt (cx, cy, w/2, h/2)
    __shared__ int    s_tid[MT];       // tgt class ids
    __shared__ float  s_cc[TN * NC];   // focal cost slice + 1.0 baked in
    __shared__ float4 s_pb[TN];        // pred (cx, cy, w/2, h/2)

    const int tid = threadIdx.x;
    const int n0  = blockIdx.x * TN;

    for (int i = tid; i < MT; i += 256) {
        float4 tb = ((const float4*)tgt_bbox)[i];
        s_tb[i] = make_float4(tb.x, tb.y, 0.5f * tb.z, 0.5f * tb.w);
        int id  = tgt_ids[i];
        s_tid[i] = (id < 0) ? 0 : (id >= NC ? NC - 1 : id);
    }
    // Fused focal-cost prep (fast-math; tolerance is 1e-3, intrinsics ~1e-6).
    // Stores cc + 1.0 so the GIoU "+1" constant is free in the main loop.
    for (int i = tid; i < TN * NC; i += 256) {
        float x = pred_logits[n0 * NC + i];
        float e = __expf(-x);
        float p = __fdividef(1.0f, 1.0f + e);
        float omp = 1.0f - p;
        float lp = __logf(p + EPSF);
        float lo = __logf(omp + EPSF);
        // cc = 0.25*omp^2*(-lp) - 0.75*p^2*(-lo)
        s_cc[i] = fmaf(-0.25f * omp * omp, lp, fmaf(0.75f * p * p, lo, 1.0f));
    }
    if (tid < TN) {
        float4 pb = ((const float4*)pred_boxes)[n0 + tid];
        s_pb[tid] = make_float4(pb.x, pb.y, 0.5f * pb.z, 0.5f * pb.w);
    }
    __syncthreads();

    // Each thread owns groups of 4 consecutive target columns (float4 stores).
    for (int g = tid; g < MT / 4; g += 256) {
        const int m0 = g * 4;

        // Per-column cache: cx, cy, hw, hh, 4*quarter-area, class byte offset
        float tcx[4], tcy[4], htw[4], hth[4], ta4[4];
        int   idb[4];
#pragma unroll
        for (int j = 0; j < 4; j++) {
            float4 tb = s_tb[m0 + j];
            tcx[j] = tb.x;
            tcy[j] = tb.y;
            htw[j] = tb.z;
            hth[j] = tb.w;
            ta4[j] = 4.0f * tb.z * tb.w;   // full tgt area
            idb[j] = s_tid[m0 + j] * 4;    // byte offset into a cc row
        }

#pragma unroll
        for (int r = 0; r < TN; r++) {
            float4 pb = s_pb[r];
            float pcx = pb.x, pcy = pb.y;
            float hpw = pb.z, hph = pb.w;
            float pa4 = 4.0f * hpw * hph;  // full pred area
            const char* ccrow = (const char*)&s_cc[r * NC];

            float4 res;
            float* rp = &res.x;
#pragma unroll
            for (int j = 0; j < 4; j++) {
                // Shared |diff| terms (serve both L1 cost and geometry)
                float dx = fabsf(pcx - tcx[j]);
                float dy = fabsf(pcy - tcy[j]);
                float sx = fabsf(hpw - htw[j]);   // 0.5|pw - tw|
                float sy = fabsf(hph - hth[j]);
                // L1: dx + dy + 2(sx + sy)
                float cb = fmaf(2.0f, sx + sy, dx + dy);
                // Interval identity (halves cancel): overlap_w = (hpw+htw) - max(dx, sx)
                float ax = hpw + htw[j];
                float ay = hph + hth[j];
                float bx = fmaxf(dx, sx);
                float by = fmaxf(dy, sy);
                float iw = fmaxf(ax - bx, 0.0f);  // full intersection width
                float ih = fmaxf(ay - by, 0.0f);
                float inter = iw * ih;                    // full intersection area
                float uni   = (pa4 + ta4[j]) - inter;     // full union
                float ea    = (ax + bx) * (ay + by);      // full enclosing area
                // One reciprocal serves both ratios:
                //   iou = inter*ea * rcp(uni*ea),  q = uni/ea = uni*uni * rcp(uni*ea)
                float denom = uni * ea;
                float rd;
                asm("rcp.approx.f32 %0, %1;" : "=f"(rd) : "f"(denom));
                float iou = inter * ea * rd;
                float q   = uni * uni * rd;
                // cost = cb + (cc+1) - iou - q   (the +1 is baked into s_cc)
                float cc1 = *(const float*)(ccrow + idb[j]);   // LDS [reg + imm]
                rp[j] = (cb + cc1) - (iou + q);
            }
            ((float4*)out)[((size_t)(n0 + r) * MT + m0) >> 2] = res;
        }
    }
}

extern "C" void kernel_launch(void* const* d_in, const int* in_sizes, int n_in,
                              void* d_out, int out_size) {
    const float* pred_logits = (const float*)d_in[0];  // [16,900,91]
    const float* pred_boxes  = (const float*)d_in[1];  // [16,900,4]
    const int*   tgt_ids     = (const int*)d_in[2];    // [1600] int32
    const float* tgt_bbox    = (const float*)d_in[3];  // [1600,4]
    float*       out         = (float*)d_out;          // [16,900,1600]

    cost_kernel<<<NROWS / TN, 256>>>(pred_logits, pred_boxes, tgt_ids, tgt_bbox, out);
}